// round 9
// baseline (speedup 1.0000x reference)
#include <cuda_runtime.h>
#include <cstdint>

#define NS      500000
#define NGENES  20000
#define NNODES  600000
#define NB      64
#define H1      1024
#define H2      256

#define NT      (NS / 32)          // 15625 SNP tiles
#define CAP     128                // fixed bucket capacity (mean 38.4, max ~66)

// ---------------- scratch (static device globals; no allocation) ----------------
static __device__ float d_geneT[NGENES * NB];   // [g][b]
static __device__ float d_h1v[H1 * NB];         // [o][b]
static __device__ float d_h2v[H2 * NB];         // [p][b]
static __device__ int   d_cur[NT];              // per-tile fill cursors
static __device__ int   d_entry[NT * CAP];      // packed: gene | (s_local<<15)

// ---------------- helpers ----------------
__device__ __forceinline__ unsigned long long fma2(unsigned long long a,
                                                   unsigned long long b,
                                                   unsigned long long c) {
    unsigned long long d;
    asm("fma.rn.f32x2 %0, %1, %2, %3;" : "=l"(d) : "l"(a), "l"(b), "l"(c));
    return d;
}

__device__ __forceinline__ unsigned long long splat2(float v) {
    unsigned long long d;
    asm("mov.b64 %0, {%1, %1};" : "=l"(d) : "r"(__float_as_uint(v)));
    return d;
}

__device__ __forceinline__ void red_add_v4(float* p, float a, float b, float c, float d) {
    asm volatile("red.global.add.v4.f32 [%0], {%1, %2, %3, %4};"
                 :: "l"(p), "f"(a), "f"(b), "f"(c), "f"(d) : "memory");
}

__device__ __forceinline__ void red_add_v2(float* p, float a, float b) {
    asm volatile("red.global.add.v2.f32 [%0], {%1, %2};"
                 :: "l"(p), "f"(a), "f"(b) : "memory");
}

__device__ __forceinline__ unsigned int to_tf32(float x) {
    unsigned int o;
    asm("cvt.rna.tf32.f32 %0, %1;" : "=r"(o) : "f"(x));
    return o;
}

__device__ __forceinline__ void mma_tf32(float& c0, float& c1, float& c2, float& c3,
                                         unsigned int a0, unsigned int a1,
                                         unsigned int a2, unsigned int a3,
                                         unsigned int b0, unsigned int b1) {
    asm("mma.sync.aligned.m16n8k8.row.col.f32.tf32.tf32.f32 "
        "{%0,%1,%2,%3}, {%4,%5,%6,%7}, {%8,%9}, {%0,%1,%2,%3};"
        : "+f"(c0), "+f"(c1), "+f"(c2), "+f"(c3)
        : "r"(a0), "r"(a1), "r"(a2), "r"(a3), "r"(b0), "r"(b1));
}

// ---------------- zero ----------------
__global__ void zero_kernel() {
    int i = blockIdx.x * blockDim.x + threadIdx.x;
    const int n0 = NGENES * NB;
    const int n1 = n0 + H1 * NB;
    const int n2 = n1 + H2 * NB;
    const int n3 = n2 + NT;
    if (i < n0)       d_geneT[i] = 0.f;
    else if (i < n1)  d_h1v[i - n0] = 0.f;
    else if (i < n2)  d_h2v[i - n1] = 0.f;
    else if (i < n3)  d_cur[i - n2] = 0;
}

// ---------------- bucket fill (4 nodes/thread) ----------------
__global__ void fill_kernel(const int* __restrict__ snp_ids,
                            const int* __restrict__ node_gene) {
    int j0 = (blockIdx.x * blockDim.x + threadIdx.x) * 4;
    if (j0 >= NNODES) return;
    int4 s4 = *reinterpret_cast<const int4*>(&snp_ids[j0]);
    int4 g4 = *reinterpret_cast<const int4*>(&node_gene[j0]);
    int t0 = s4.x >> 5, t1 = s4.y >> 5, t2 = s4.z >> 5, t3 = s4.w >> 5;
    int p0 = atomicAdd(&d_cur[t0], 1);
    int p1 = atomicAdd(&d_cur[t1], 1);
    int p2 = atomicAdd(&d_cur[t2], 1);
    int p3 = atomicAdd(&d_cur[t3], 1);
    if (p0 < CAP) d_entry[t0 * CAP + p0] = g4.x | ((s4.x & 31) << 15);
    if (p1 < CAP) d_entry[t1 * CAP + p1] = g4.y | ((s4.y & 31) << 15);
    if (p2 < CAP) d_entry[t2 * CAP + p2] = g4.z | ((s4.z & 31) << 15);
    if (p3 < CAP) d_entry[t3 * CAP + p3] = g4.w | ((s4.w & 31) << 15);
}

// ---------------- fused transpose + scatter ----------------
__global__ void __launch_bounds__(256)
fused_scatter_kernel(const float* __restrict__ snp,
                     const float* __restrict__ filters) {
    __shared__ float tile[32][68];
    __shared__ float wv[32];
    const int s0 = blockIdx.x * 32;
    const int t  = threadIdx.x;

    if (t < 32) {
        float acc = 0.f;
#pragma unroll
        for (int f = 0; f < 8; f++) acc += filters[(size_t)f * NS + s0 + t];
        wv[t] = acc * 0.125f;
    }
    {
        const int sl = t & 31, brow = t >> 5;
#pragma unroll
        for (int i = 0; i < 8; i++) {
            int b = brow + i * 8;
            tile[sl][b] = snp[(size_t)b * NS + s0 + sl];
        }
    }
    __syncthreads();

    const int base  = blockIdx.x * CAP;
    int total = d_cur[blockIdx.x];
    if (total > CAP) total = CAP;
    const int q = t & 15;

    for (int c = t >> 4; c < total; c += 16) {
        int v  = d_entry[base + c];
        int g  = v & 0x7FFF;
        int sl = v >> 15;
        float w = wv[sl];
        float4 x = *reinterpret_cast<const float4*>(&tile[sl][q * 4]);
        red_add_v4(&d_geneT[g * NB + q * 4], x.x * w, x.y * w, x.z * w, x.w * w);
    }
}

// ---------------- GEMM1: tf32, register double-buffered staging ----------------
__global__ void __launch_bounds__(256)
gemm1_tf32_kernel(const float* __restrict__ gene,
                  const float* __restrict__ W1,
                  float* __restrict__ C,
                  int kchunk) {
    __shared__ unsigned int Ws[16][136];   // W1 tile [k][128 feat], pad 8
    __shared__ unsigned int Gs[16][72];    // gene tile [k][64 b],  pad 8

    const int f0 = blockIdx.x * 128;
    const int k0 = blockIdx.y * kchunk;
    const int t  = threadIdx.x;
    const int w  = t >> 5, l = t & 31;
    const int g4 = l >> 2, tg = l & 3;

    float acc[8][4] = {};

    const unsigned int* smW = &Ws[0][0];
    const unsigned int* smG = &Gs[0][0];
    const int aBase = tg * 136 + w * 16 + g4;
    const int bBase = tg * 72 + g4;

    // staging indices
    const int gRow = t >> 4,  gCol = (t & 15) * 4;       // gene 16x64
    const int wRow0 = t >> 5,        wCol0 = (t & 31) * 4;   // W 16x128 (two halves)
    const int wRow1 = (t + 256) >> 5, wCol1 = wCol0;

    const int iters = kchunk >> 4;

    // prologue: load chunk 0 into registers
    float4 rG  = *reinterpret_cast<const float4*>(&gene[(size_t)(k0 + gRow) * NB + gCol]);
    float4 rW0 = *reinterpret_cast<const float4*>(&W1[(size_t)(k0 + wRow0) * H1 + f0 + wCol0]);
    float4 rW1 = *reinterpret_cast<const float4*>(&W1[(size_t)(k0 + wRow1) * H1 + f0 + wCol1]);

    for (int it = 0; it < iters; it++) {
        {   // commit staged registers to smem (with tf32 rounding)
            uint4 og = { to_tf32(rG.x), to_tf32(rG.y), to_tf32(rG.z), to_tf32(rG.w) };
            *reinterpret_cast<uint4*>(&Gs[gRow][gCol]) = og;
            uint4 o0 = { to_tf32(rW0.x), to_tf32(rW0.y), to_tf32(rW0.z), to_tf32(rW0.w) };
            *reinterpret_cast<uint4*>(&Ws[wRow0][wCol0]) = o0;
            uint4 o1 = { to_tf32(rW1.x), to_tf32(rW1.y), to_tf32(rW1.z), to_tf32(rW1.w) };
            *reinterpret_cast<uint4*>(&Ws[wRow1][wCol1]) = o1;
        }
        __syncthreads();

        if (it + 1 < iters) {   // issue next chunk's loads; latency hides under MMAs
            const int kb = k0 + (it + 1) * 16;
            rG  = *reinterpret_cast<const float4*>(&gene[(size_t)(kb + gRow) * NB + gCol]);
            rW0 = *reinterpret_cast<const float4*>(&W1[(size_t)(kb + wRow0) * H1 + f0 + wCol0]);
            rW1 = *reinterpret_cast<const float4*>(&W1[(size_t)(kb + wRow1) * H1 + f0 + wCol1]);
        }

#pragma unroll
        for (int ks = 0; ks < 2; ks++) {
            const unsigned int* pa = smW + aBase + ks * (8 * 136);
            unsigned int a0 = pa[0];
            unsigned int a1 = pa[8];
            unsigned int a2 = pa[4 * 136];
            unsigned int a3 = pa[4 * 136 + 8];
            const unsigned int* pb = smG + bBase + ks * (8 * 72);
#pragma unroll
            for (int j = 0; j < 8; j++) {
                unsigned int b0 = pb[j * 8];
                unsigned int b1 = pb[j * 8 + 4 * 72];
                mma_tf32(acc[j][0], acc[j][1], acc[j][2], acc[j][3],
                         a0, a1, a2, a3, b0, b1);
            }
        }
        __syncthreads();
    }

    const int featA = f0 + w * 16 + g4;
    const int bcol0 = tg * 2;
#pragma unroll
    for (int j = 0; j < 8; j++) {
        float* cp = &C[(size_t)featA * NB + j * 8 + bcol0];
        red_add_v2(cp, acc[j][0], acc[j][1]);
        red_add_v2(cp + 8 * NB, acc[j][2], acc[j][3]);
    }
}

// ---------------- GEMM2 (f32x2, 64m x 128n tile, split-K with red.v4) ----------------
__global__ void __launch_bounds__(256)
gemm_kernel(const float* __restrict__ A,
            const float* __restrict__ W,
            float* __restrict__ C,
            int N, int kchunk) {
    __shared__ float As[16][64];
    __shared__ float Bs[16][128];

    const int n0 = blockIdx.x * 128;
    const int k0 = blockIdx.y * kchunk;
    const int t  = threadIdx.x;
    const int w  = t >> 5, l = t & 31;

    unsigned long long acc[4][4] = {};

    const float4* A4 = reinterpret_cast<const float4*>(A);
    const float4* W4 = reinterpret_cast<const float4*>(W);
    const int n4 = N >> 2;

    const int arow = t >> 4, ac = t & 15;
    const int brow = t >> 5, bc = t & 31;

    for (int kc = 0; kc < kchunk; kc += 16) {
        const int kb = k0 + kc;
        reinterpret_cast<float4*>(&As[arow][0])[ac] =
            A4[(size_t)(kb + arow) * 16 + ac];
        reinterpret_cast<float4*>(&Bs[brow][0])[bc] =
            W4[(size_t)(kb + brow) * n4 + (n0 >> 2) + bc];
        reinterpret_cast<float4*>(&Bs[brow + 8][0])[bc] =
            W4[(size_t)(kb + brow + 8) * n4 + (n0 >> 2) + bc];
        __syncthreads();

#pragma unroll
        for (int kk = 0; kk < 16; kk++) {
            ulonglong2 a01 = reinterpret_cast<const ulonglong2*>(&As[kk][w * 8])[0];
            ulonglong2 a23 = reinterpret_cast<const ulonglong2*>(&As[kk][w * 8])[1];
            float4 bv = reinterpret_cast<const float4*>(&Bs[kk][0])[l];
            unsigned long long b0 = splat2(bv.x), b1 = splat2(bv.y);
            unsigned long long b2 = splat2(bv.z), b3 = splat2(bv.w);

            acc[0][0] = fma2(a01.x, b0, acc[0][0]);
            acc[0][1] = fma2(a01.y, b0, acc[0][1]);
            acc[0][2] = fma2(a23.x, b0, acc[0][2]);
            acc[0][3] = fma2(a23.y, b0, acc[0][3]);
            acc[1][0] = fma2(a01.x, b1, acc[1][0]);
            acc[1][1] = fma2(a01.y, b1, acc[1][1]);
            acc[1][2] = fma2(a23.x, b1, acc[1][2]);
            acc[1][3] = fma2(a23.y, b1, acc[1][3]);
            acc[2][0] = fma2(a01.x, b2, acc[2][0]);
            acc[2][1] = fma2(a01.y, b2, acc[2][1]);
            acc[2][2] = fma2(a23.x, b2, acc[2][2]);
            acc[2][3] = fma2(a23.y, b2, acc[2][3]);
            acc[3][0] = fma2(a01.x, b3, acc[3][0]);
            acc[3][1] = fma2(a01.y, b3, acc[3][1]);
            acc[3][2] = fma2(a23.x, b3, acc[3][2]);
            acc[3][3] = fma2(a23.y, b3, acc[3][3]);
        }
        __syncthreads();
    }

#pragma unroll
    for (int i = 0; i < 4; i++) {
        int n = n0 + l * 4 + i;
        float* cp = &C[(size_t)n * NB + w * 8];
        float2 p0 = *reinterpret_cast<float2*>(&acc[i][0]);
        float2 p1 = *reinterpret_cast<float2*>(&acc[i][1]);
        float2 p2 = *reinterpret_cast<float2*>(&acc[i][2]);
        float2 p3 = *reinterpret_cast<float2*>(&acc[i][3]);
        red_add_v4(cp,     p0.x, p0.y, p1.x, p1.y);
        red_add_v4(cp + 4, p2.x, p2.y, p3.x, p3.y);
    }
}

// ---------------- batchnorm + relu (h1 only) ----------------
__global__ void bn_relu_kernel(float* __restrict__ h,
                               const float* __restrict__ gamma,
                               const float* __restrict__ beta, int R) {
    int warp = (blockIdx.x * blockDim.x + threadIdx.x) >> 5;
    int lane = threadIdx.x & 31;
    if (warp >= R) return;
    float* row = h + warp * NB;
    float x0 = row[lane], x1 = row[lane + 32];
    float s = x0 + x1, sq = x0 * x0 + x1 * x1;
#pragma unroll
    for (int o = 16; o; o >>= 1) {
        s  += __shfl_xor_sync(0xffffffffu, s, o);
        sq += __shfl_xor_sync(0xffffffffu, sq, o);
    }
    float m = s * (1.f / 64.f);
    float v = sq * (1.f / 64.f) - m * m;
    float inv = rsqrtf(v + 1e-5f);
    float g = gamma[warp], be = beta[warp];
    row[lane]      = fmaxf(fmaf(g * (x0 - m), inv, be), 0.f);
    row[lane + 32] = fmaxf(fmaf(g * (x1 - m), inv, be), 0.f);
}

// ---------------- fused bn2 + relu + final projection ----------------
__global__ void bn_final_kernel(const float* __restrict__ gamma,
                                const float* __restrict__ beta,
                                const float* __restrict__ W3,
                                const float* __restrict__ b3,
                                float* __restrict__ out) {
    __shared__ float part[8][NB];
    const int t = threadIdx.x, lane = t & 31, w = t >> 5;
    float a0 = 0.f, a1 = 0.f;
#pragma unroll 4
    for (int r = 0; r < 32; r++) {
        int p = w * 32 + r;
        float x0 = d_h2v[p * NB + lane];
        float x1 = d_h2v[p * NB + lane + 32];
        float s = x0 + x1, sq = x0 * x0 + x1 * x1;
#pragma unroll
        for (int o = 16; o; o >>= 1) {
            s  += __shfl_xor_sync(0xffffffffu, s, o);
            sq += __shfl_xor_sync(0xffffffffu, sq, o);
        }
        float m = s * (1.f / 64.f);
        float v = sq * (1.f / 64.f) - m * m;
        float inv = rsqrtf(v + 1e-5f);
        float g = gamma[p], be = beta[p], w3 = W3[p];
        a0 += fmaxf(fmaf(g * (x0 - m), inv, be), 0.f) * w3;
        a1 += fmaxf(fmaf(g * (x1 - m), inv, be), 0.f) * w3;
    }
    part[w][lane] = a0;
    part[w][lane + 32] = a1;
    __syncthreads();
    if (t < NB) {
        float s = b3[0];
#pragma unroll
        for (int i = 0; i < 8; i++) s += part[i][t];
        out[t] = s;
    }
}

// ---------------- launch ----------------
extern "C" void kernel_launch(void* const* d_in, const int* in_sizes, int n_in,
                              void* d_out, int out_size) {
    const float* snp       = (const float*)d_in[0];
    const int*   snp_ids   = (const int*)  d_in[1];
    const int*   node_gene = (const int*)  d_in[2];
    const float* filters   = (const float*)d_in[3];
    const float* W1        = (const float*)d_in[4];
    // b1 = d_in[5] (cancels under batch-stat BN)
    const float* g1        = (const float*)d_in[6];
    const float* beta1     = (const float*)d_in[7];
    const float* W2        = (const float*)d_in[8];
    // b2 = d_in[9] (cancels)
    const float* g2        = (const float*)d_in[10];
    const float* beta2     = (const float*)d_in[11];
    const float* W3        = (const float*)d_in[12];
    const float* b3        = (const float*)d_in[13];
    float* out = (float*)d_out;

    void *pGene = nullptr, *pH1 = nullptr, *pH2 = nullptr;
    cudaGetSymbolAddress(&pGene, d_geneT);
    cudaGetSymbolAddress(&pH1,   d_h1v);
    cudaGetSymbolAddress(&pH2,   d_h2v);

    {
        const int total = NGENES * NB + H1 * NB + H2 * NB + NT;
        zero_kernel<<<(total + 255) / 256, 256>>>();
    }

    // bucket fill (fixed-capacity CSR, no histogram/scan)
    fill_kernel<<<(NNODES / 4 + 255) / 256, 256>>>(snp_ids, node_gene);

    // fused transpose + scatter
    fused_scatter_kernel<<<NT, 256>>>(snp, filters);

    // GEMM1: tf32 tensor cores, double-buffered. 8 feat-tiles x 50 k-splits
    gemm1_tf32_kernel<<<dim3(8, 50), 256>>>((const float*)pGene, W1, (float*)pH1, 400);
    bn_relu_kernel<<<H1 * 32 / 256, 256>>>((float*)pH1, g1, beta1, H1);

    // GEMM2: N=256 -> 2 n-tiles; K=1024 split 16 x 64
    gemm_kernel<<<dim3(2, 16), 256>>>((const float*)pH1, W2, (float*)pH2, 256, 64);

    // fused bn2 + relu + final projection
    bn_final_kernel<<<1, 256>>>(g2, beta2, W3, b3, out);

    // second reference output: filters passthrough
    if (out_size > NB) {
        cudaMemcpyAsync(out + NB, filters,
                        (size_t)(out_size - NB) * sizeof(float),
                        cudaMemcpyDeviceToDevice);
    }
}

// round 10
// speedup vs baseline: 1.0521x; 1.0521x over previous
#include <cuda_runtime.h>
#include <cstdint>

#define NS      500000
#define NGENES  20000
#define NNODES  600000
#define NB      64
#define H1      1024
#define H2      256

#define NT      (NS / 32)          // 15625 SNP tiles
#define CAP     128                // fixed bucket capacity (mean 38.4, max ~66)

// ---------------- scratch (static device globals; no allocation) ----------------
static __device__ float d_geneT[NGENES * NB];   // [g][b]
static __device__ float d_h1v[H1 * NB];         // [o][b]
static __device__ float d_h2v[H2 * NB];         // [p][b]
static __device__ int   d_cur[NT];              // per-tile fill cursors
static __device__ int   d_entry[NT * CAP];      // packed: gene | (s_local<<15)

// ---------------- helpers ----------------
__device__ __forceinline__ unsigned long long fma2(unsigned long long a,
                                                   unsigned long long b,
                                                   unsigned long long c) {
    unsigned long long d;
    asm("fma.rn.f32x2 %0, %1, %2, %3;" : "=l"(d) : "l"(a), "l"(b), "l"(c));
    return d;
}

__device__ __forceinline__ unsigned long long splat2(float v) {
    unsigned long long d;
    asm("mov.b64 %0, {%1, %1};" : "=l"(d) : "r"(__float_as_uint(v)));
    return d;
}

__device__ __forceinline__ void red_add_v4(float* p, float a, float b, float c, float d) {
    asm volatile("red.global.add.v4.f32 [%0], {%1, %2, %3, %4};"
                 :: "l"(p), "f"(a), "f"(b), "f"(c), "f"(d) : "memory");
}

__device__ __forceinline__ void red_add_v2(float* p, float a, float b) {
    asm volatile("red.global.add.v2.f32 [%0], {%1, %2};"
                 :: "l"(p), "f"(a), "f"(b) : "memory");
}

__device__ __forceinline__ unsigned int to_tf32(float x) {
    unsigned int o;
    asm("cvt.rna.tf32.f32 %0, %1;" : "=r"(o) : "f"(x));
    return o;
}

__device__ __forceinline__ void mma_tf32(float& c0, float& c1, float& c2, float& c3,
                                         unsigned int a0, unsigned int a1,
                                         unsigned int a2, unsigned int a3,
                                         unsigned int b0, unsigned int b1) {
    asm("mma.sync.aligned.m16n8k8.row.col.f32.tf32.tf32.f32 "
        "{%0,%1,%2,%3}, {%4,%5,%6,%7}, {%8,%9}, {%0,%1,%2,%3};"
        : "+f"(c0), "+f"(c1), "+f"(c2), "+f"(c3)
        : "r"(a0), "r"(a1), "r"(a2), "r"(a3), "r"(b0), "r"(b1));
}

// ---------------- zero ----------------
__global__ void zero_kernel() {
    int i = blockIdx.x * blockDim.x + threadIdx.x;
    const int n0 = NGENES * NB;
    const int n1 = n0 + H1 * NB;
    const int n2 = n1 + H2 * NB;
    const int n3 = n2 + NT;
    if (i < n0)       d_geneT[i] = 0.f;
    else if (i < n1)  d_h1v[i - n0] = 0.f;
    else if (i < n2)  d_h2v[i - n1] = 0.f;
    else if (i < n3)  d_cur[i - n2] = 0;
}

// ---------------- bucket fill (4 nodes/thread) ----------------
__global__ void fill_kernel(const int* __restrict__ snp_ids,
                            const int* __restrict__ node_gene) {
    int j0 = (blockIdx.x * blockDim.x + threadIdx.x) * 4;
    if (j0 >= NNODES) return;
    int4 s4 = *reinterpret_cast<const int4*>(&snp_ids[j0]);
    int4 g4 = *reinterpret_cast<const int4*>(&node_gene[j0]);
    int t0 = s4.x >> 5, t1 = s4.y >> 5, t2 = s4.z >> 5, t3 = s4.w >> 5;
    int p0 = atomicAdd(&d_cur[t0], 1);
    int p1 = atomicAdd(&d_cur[t1], 1);
    int p2 = atomicAdd(&d_cur[t2], 1);
    int p3 = atomicAdd(&d_cur[t3], 1);
    if (p0 < CAP) d_entry[t0 * CAP + p0] = g4.x | ((s4.x & 31) << 15);
    if (p1 < CAP) d_entry[t1 * CAP + p1] = g4.y | ((s4.y & 31) << 15);
    if (p2 < CAP) d_entry[t2 * CAP + p2] = g4.z | ((s4.z & 31) << 15);
    if (p3 < CAP) d_entry[t3 * CAP + p3] = g4.w | ((s4.w & 31) << 15);
}

// ---------------- fused transpose + scatter ----------------
__global__ void __launch_bounds__(256)
fused_scatter_kernel(const float* __restrict__ snp,
                     const float* __restrict__ filters) {
    __shared__ float tile[32][68];
    __shared__ float wv[32];
    const int s0 = blockIdx.x * 32;
    const int t  = threadIdx.x;

    // issue bucket-count load early so its latency overlaps the transpose
    int total = d_cur[blockIdx.x];

    if (t < 32) {
        float acc = 0.f;
#pragma unroll
        for (int f = 0; f < 8; f++) acc += filters[(size_t)f * NS + s0 + t];
        wv[t] = acc * 0.125f;
    }
    {
        const int sl = t & 31, brow = t >> 5;
#pragma unroll
        for (int i = 0; i < 8; i++) {
            int b = brow + i * 8;
            tile[sl][b] = snp[(size_t)b * NS + s0 + sl];
        }
    }
    __syncthreads();

    const int base = blockIdx.x * CAP;
    if (total > CAP) total = CAP;
    const int q = t & 15;

    for (int c = t >> 4; c < total; c += 16) {
        int v  = d_entry[base + c];
        int g  = v & 0x7FFF;
        int sl = v >> 15;
        float w = wv[sl];
        float4 x = *reinterpret_cast<const float4*>(&tile[sl][q * 4]);
        red_add_v4(&d_geneT[g * NB + q * 4], x.x * w, x.y * w, x.z * w, x.w * w);
    }
}

// ---------------- GEMM1: tf32 tensor-core, 128feat x 64batch tile, split-K ----------------
__global__ void __launch_bounds__(256)
gemm1_tf32_kernel(const float* __restrict__ gene,
                  const float* __restrict__ W1,
                  float* __restrict__ C,
                  int kchunk) {
    __shared__ unsigned int Ws[16][136];   // W1 tile [k][128 feat], pad 8
    __shared__ unsigned int Gs[16][72];    // gene tile [k][64 b],  pad 8

    const int f0 = blockIdx.x * 128;
    const int k0 = blockIdx.y * kchunk;
    const int t  = threadIdx.x;
    const int w  = t >> 5, l = t & 31;
    const int g4 = l >> 2, tg = l & 3;

    float acc[8][4] = {};

    const unsigned int* smW = &Ws[0][0];
    const unsigned int* smG = &Gs[0][0];
    const int aBase = tg * 136 + w * 16 + g4;
    const int bBase = tg * 72 + g4;

    for (int kc = 0; kc < kchunk; kc += 16) {
        const int kb = k0 + kc;
        {   // stage gene tile: 16 x 64
            int row = t >> 4, c4 = (t & 15) * 4;
            float4 v = *reinterpret_cast<const float4*>(&gene[(size_t)(kb + row) * NB + c4]);
            uint4 o = { to_tf32(v.x), to_tf32(v.y), to_tf32(v.z), to_tf32(v.w) };
            *reinterpret_cast<uint4*>(&Gs[row][c4]) = o;
        }
        {   // stage W1 tile: 16 x 128
#pragma unroll
            for (int i = 0; i < 2; i++) {
                int idx = t + i * 256;
                int row = idx >> 5, c4 = (idx & 31) * 4;
                float4 v = *reinterpret_cast<const float4*>(
                    &W1[(size_t)(kb + row) * H1 + f0 + c4]);
                uint4 o = { to_tf32(v.x), to_tf32(v.y), to_tf32(v.z), to_tf32(v.w) };
                *reinterpret_cast<uint4*>(&Ws[row][c4]) = o;
            }
        }
        __syncthreads();

#pragma unroll
        for (int ks = 0; ks < 2; ks++) {
            const unsigned int* pa = smW + aBase + ks * (8 * 136);
            unsigned int a0 = pa[0];
            unsigned int a1 = pa[8];
            unsigned int a2 = pa[4 * 136];
            unsigned int a3 = pa[4 * 136 + 8];
            const unsigned int* pb = smG + bBase + ks * (8 * 72);
#pragma unroll
            for (int j = 0; j < 8; j++) {
                unsigned int b0 = pb[j * 8];
                unsigned int b1 = pb[j * 8 + 4 * 72];
                mma_tf32(acc[j][0], acc[j][1], acc[j][2], acc[j][3],
                         a0, a1, a2, a3, b0, b1);
            }
        }
        __syncthreads();
    }

    const int featA = f0 + w * 16 + g4;
    const int bcol0 = tg * 2;
#pragma unroll
    for (int j = 0; j < 8; j++) {
        float* cp = &C[(size_t)featA * NB + j * 8 + bcol0];
        red_add_v2(cp, acc[j][0], acc[j][1]);
        red_add_v2(cp + 8 * NB, acc[j][2], acc[j][3]);
    }
}

// ---------------- GEMM2 (f32x2, 64m x 128n tile, split-K with red.v4) ----------------
__global__ void __launch_bounds__(256)
gemm_kernel(const float* __restrict__ A,
            const float* __restrict__ W,
            float* __restrict__ C,
            int N, int kchunk) {
    __shared__ float As[16][64];
    __shared__ float Bs[16][128];

    const int n0 = blockIdx.x * 128;
    const int k0 = blockIdx.y * kchunk;
    const int t  = threadIdx.x;
    const int w  = t >> 5, l = t & 31;

    unsigned long long acc[4][4] = {};

    const float4* A4 = reinterpret_cast<const float4*>(A);
    const float4* W4 = reinterpret_cast<const float4*>(W);
    const int n4 = N >> 2;

    const int arow = t >> 4, ac = t & 15;
    const int brow = t >> 5, bc = t & 31;

    for (int kc = 0; kc < kchunk; kc += 16) {
        const int kb = k0 + kc;
        reinterpret_cast<float4*>(&As[arow][0])[ac] =
            A4[(size_t)(kb + arow) * 16 + ac];
        reinterpret_cast<float4*>(&Bs[brow][0])[bc] =
            W4[(size_t)(kb + brow) * n4 + (n0 >> 2) + bc];
        reinterpret_cast<float4*>(&Bs[brow + 8][0])[bc] =
            W4[(size_t)(kb + brow + 8) * n4 + (n0 >> 2) + bc];
        __syncthreads();

#pragma unroll
        for (int kk = 0; kk < 16; kk++) {
            ulonglong2 a01 = reinterpret_cast<const ulonglong2*>(&As[kk][w * 8])[0];
            ulonglong2 a23 = reinterpret_cast<const ulonglong2*>(&As[kk][w * 8])[1];
            float4 bv = reinterpret_cast<const float4*>(&Bs[kk][0])[l];
            unsigned long long b0 = splat2(bv.x), b1 = splat2(bv.y);
            unsigned long long b2 = splat2(bv.z), b3 = splat2(bv.w);

            acc[0][0] = fma2(a01.x, b0, acc[0][0]);
            acc[0][1] = fma2(a01.y, b0, acc[0][1]);
            acc[0][2] = fma2(a23.x, b0, acc[0][2]);
            acc[0][3] = fma2(a23.y, b0, acc[0][3]);
            acc[1][0] = fma2(a01.x, b1, acc[1][0]);
            acc[1][1] = fma2(a01.y, b1, acc[1][1]);
            acc[1][2] = fma2(a23.x, b1, acc[1][2]);
            acc[1][3] = fma2(a23.y, b1, acc[1][3]);
            acc[2][0] = fma2(a01.x, b2, acc[2][0]);
            acc[2][1] = fma2(a01.y, b2, acc[2][1]);
            acc[2][2] = fma2(a23.x, b2, acc[2][2]);
            acc[2][3] = fma2(a23.y, b2, acc[2][3]);
            acc[3][0] = fma2(a01.x, b3, acc[3][0]);
            acc[3][1] = fma2(a01.y, b3, acc[3][1]);
            acc[3][2] = fma2(a23.x, b3, acc[3][2]);
            acc[3][3] = fma2(a23.y, b3, acc[3][3]);
        }
        __syncthreads();
    }

#pragma unroll
    for (int i = 0; i < 4; i++) {
        int n = n0 + l * 4 + i;
        float* cp = &C[(size_t)n * NB + w * 8];
        float2 p0 = *reinterpret_cast<float2*>(&acc[i][0]);
        float2 p1 = *reinterpret_cast<float2*>(&acc[i][1]);
        float2 p2 = *reinterpret_cast<float2*>(&acc[i][2]);
        float2 p3 = *reinterpret_cast<float2*>(&acc[i][3]);
        red_add_v4(cp,     p0.x, p0.y, p1.x, p1.y);
        red_add_v4(cp + 4, p2.x, p2.y, p3.x, p3.y);
    }
}

// ---------------- batchnorm + relu (h1 only) ----------------
__global__ void bn_relu_kernel(float* __restrict__ h,
                               const float* __restrict__ gamma,
                               const float* __restrict__ beta, int R) {
    int warp = (blockIdx.x * blockDim.x + threadIdx.x) >> 5;
    int lane = threadIdx.x & 31;
    if (warp >= R) return;
    float* row = h + warp * NB;
    float x0 = row[lane], x1 = row[lane + 32];
    float s = x0 + x1, sq = x0 * x0 + x1 * x1;
#pragma unroll
    for (int o = 16; o; o >>= 1) {
        s  += __shfl_xor_sync(0xffffffffu, s, o);
        sq += __shfl_xor_sync(0xffffffffu, sq, o);
    }
    float m = s * (1.f / 64.f);
    float v = sq * (1.f / 64.f) - m * m;
    float inv = rsqrtf(v + 1e-5f);
    float g = gamma[warp], be = beta[warp];
    row[lane]      = fmaxf(fmaf(g * (x0 - m), inv, be), 0.f);
    row[lane + 32] = fmaxf(fmaf(g * (x1 - m), inv, be), 0.f);
}

// ---------------- fused bn2 + relu + final projection ----------------
__global__ void bn_final_kernel(const float* __restrict__ gamma,
                                const float* __restrict__ beta,
                                const float* __restrict__ W3,
                                const float* __restrict__ b3,
                                float* __restrict__ out) {
    __shared__ float part[8][NB];
    const int t = threadIdx.x, lane = t & 31, w = t >> 5;
    float a0 = 0.f, a1 = 0.f;
#pragma unroll 4
    for (int r = 0; r < 32; r++) {
        int p = w * 32 + r;
        float x0 = d_h2v[p * NB + lane];
        float x1 = d_h2v[p * NB + lane + 32];
        float s = x0 + x1, sq = x0 * x0 + x1 * x1;
#pragma unroll
        for (int o = 16; o; o >>= 1) {
            s  += __shfl_xor_sync(0xffffffffu, s, o);
            sq += __shfl_xor_sync(0xffffffffu, sq, o);
        }
        float m = s * (1.f / 64.f);
        float v = sq * (1.f / 64.f) - m * m;
        float inv = rsqrtf(v + 1e-5f);
        float g = gamma[p], be = beta[p], w3 = W3[p];
        a0 += fmaxf(fmaf(g * (x0 - m), inv, be), 0.f) * w3;
        a1 += fmaxf(fmaf(g * (x1 - m), inv, be), 0.f) * w3;
    }
    part[w][lane] = a0;
    part[w][lane + 32] = a1;
    __syncthreads();
    if (t < NB) {
        float s = b3[0];
#pragma unroll
        for (int i = 0; i < 8; i++) s += part[i][t];
        out[t] = s;
    }
}

// ---------------- launch ----------------
extern "C" void kernel_launch(void* const* d_in, const int* in_sizes, int n_in,
                              void* d_out, int out_size) {
    const float* snp       = (const float*)d_in[0];
    const int*   snp_ids   = (const int*)  d_in[1];
    const int*   node_gene = (const int*)  d_in[2];
    const float* filters   = (const float*)d_in[3];
    const float* W1        = (const float*)d_in[4];
    // b1 = d_in[5] (cancels under batch-stat BN)
    const float* g1        = (const float*)d_in[6];
    const float* beta1     = (const float*)d_in[7];
    const float* W2        = (const float*)d_in[8];
    // b2 = d_in[9] (cancels)
    const float* g2        = (const float*)d_in[10];
    const float* beta2     = (const float*)d_in[11];
    const float* W3        = (const float*)d_in[12];
    const float* b3        = (const float*)d_in[13];
    float* out = (float*)d_out;

    void *pGene = nullptr, *pH1 = nullptr, *pH2 = nullptr;
    cudaGetSymbolAddress(&pGene, d_geneT);
    cudaGetSymbolAddress(&pH1,   d_h1v);
    cudaGetSymbolAddress(&pH2,   d_h2v);

    {
        const int total = NGENES * NB + H1 * NB + H2 * NB + NT;
        zero_kernel<<<(total + 255) / 256, 256>>>();
    }

    // bucket fill (fixed-capacity CSR, no histogram/scan)
    fill_kernel<<<(NNODES / 4 + 255) / 256, 256>>>(snp_ids, node_gene);

    // fused transpose + scatter
    fused_scatter_kernel<<<NT, 256>>>(snp, filters);

    // GEMM1: tf32 tensor cores. 8 feat-tiles x 125 k-splits (kchunk 160)
    gemm1_tf32_kernel<<<dim3(8, 125), 256>>>((const float*)pGene, W1, (float*)pH1, 160);
    bn_relu_kernel<<<H1 * 32 / 256, 256>>>((float*)pH1, g1, beta1, H1);

    // GEMM2: N=256 -> 2 n-tiles; K=1024 split 16 x 64
    gemm_kernel<<<dim3(2, 16), 256>>>((const float*)pH1, W2, (float*)pH2, 256, 64);

    // fused bn2 + relu + final projection
    bn_final_kernel<<<1, 256>>>(g2, beta2, W3, b3, out);

    // second reference output: filters passthrough
    if (out_size > NB) {
        cudaMemcpyAsync(out + NB, filters,
                        (size_t)(out_size - NB) * sizeof(float),
                        cudaMemcpyDeviceToDevice);
    }
}

// round 13
// speedup vs baseline: 1.0892x; 1.0353x over previous
#include <cuda_runtime.h>
#include <cstdint>

#define NS      500000
#define NGENES  20000
#define NNODES  600000
#define NB      64
#define H1      1024
#define H2      256

#define NT      (NS / 32)          // 15625 SNP tiles
#define CAP     128                // fixed bucket capacity (mean 38.4, max ~66)

// ---------------- scratch (static device globals; no allocation) ----------------
static __device__ float d_geneT[NGENES * NB];   // [g][b]
static __device__ float d_h1v[H1 * NB];         // [o][b]
static __device__ float d_h2v[H2 * NB];         // [p][b]
static __device__ int   d_cur[NT];              // per-tile fill cursors
static __device__ int   d_entry[NT * CAP];      // packed: gene | (s_local<<15)

// ---------------- helpers ----------------
__device__ __forceinline__ unsigned long long fma2(unsigned long long a,
                                                   unsigned long long b,
                                                   unsigned long long c) {
    unsigned long long d;
    asm("fma.rn.f32x2 %0, %1, %2, %3;" : "=l"(d) : "l"(a), "l"(b), "l"(c));
    return d;
}

__device__ __forceinline__ unsigned long long splat2(float v) {
    unsigned long long d;
    asm("mov.b64 %0, {%1, %1};" : "=l"(d) : "r"(__float_as_uint(v)));
    return d;
}

__device__ __forceinline__ void red_add_v4(float* p, float a, float b, float c, float d) {
    asm volatile("red.global.add.v4.f32 [%0], {%1, %2, %3, %4};"
                 :: "l"(p), "f"(a), "f"(b), "f"(c), "f"(d) : "memory");
}

__device__ __forceinline__ void red_add_v2(float* p, float a, float b) {
    asm volatile("red.global.add.v2.f32 [%0], {%1, %2};"
                 :: "l"(p), "f"(a), "f"(b) : "memory");
}

__device__ __forceinline__ unsigned int to_tf32(float x) {
    unsigned int o;
    asm("cvt.rna.tf32.f32 %0, %1;" : "=r"(o) : "f"(x));
    return o;
}

__device__ __forceinline__ void mma_tf32(float& c0, float& c1, float& c2, float& c3,
                                         unsigned int a0, unsigned int a1,
                                         unsigned int a2, unsigned int a3,
                                         unsigned int b0, unsigned int b1) {
    asm("mma.sync.aligned.m16n8k8.row.col.f32.tf32.tf32.f32 "
        "{%0,%1,%2,%3}, {%4,%5,%6,%7}, {%8,%9}, {%0,%1,%2,%3};"
        : "+f"(c0), "+f"(c1), "+f"(c2), "+f"(c3)
        : "r"(a0), "r"(a1), "r"(a2), "r"(a3), "r"(b0), "r"(b1));
}

__device__ __forceinline__ void cp_async16(unsigned int dst_smem, const void* src) {
    asm volatile("cp.async.cg.shared.global [%0], [%1], 16;"
                 :: "r"(dst_smem), "l"(src));
}
__device__ __forceinline__ void cp_commit() {
    asm volatile("cp.async.commit_group;");
}
__device__ __forceinline__ void cp_wait1() {
    asm volatile("cp.async.wait_group 1;");
}

// ---------------- zero ----------------
__global__ void zero_kernel() {
    int i = blockIdx.x * blockDim.x + threadIdx.x;
    const int n0 = NGENES * NB;
    const int n1 = n0 + H1 * NB;
    const int n2 = n1 + H2 * NB;
    const int n3 = n2 + NT;
    if (i < n0)       d_geneT[i] = 0.f;
    else if (i < n1)  d_h1v[i - n0] = 0.f;
    else if (i < n2)  d_h2v[i - n1] = 0.f;
    else if (i < n3)  d_cur[i - n2] = 0;
}

// ---------------- bucket fill (4 nodes/thread) ----------------
__global__ void fill_kernel(const int* __restrict__ snp_ids,
                            const int* __restrict__ node_gene) {
    int j0 = (blockIdx.x * blockDim.x + threadIdx.x) * 4;
    if (j0 >= NNODES) return;
    int4 s4 = *reinterpret_cast<const int4*>(&snp_ids[j0]);
    int4 g4 = *reinterpret_cast<const int4*>(&node_gene[j0]);
    int t0 = s4.x >> 5, t1 = s4.y >> 5, t2 = s4.z >> 5, t3 = s4.w >> 5;
    int p0 = atomicAdd(&d_cur[t0], 1);
    int p1 = atomicAdd(&d_cur[t1], 1);
    int p2 = atomicAdd(&d_cur[t2], 1);
    int p3 = atomicAdd(&d_cur[t3], 1);
    if (p0 < CAP) d_entry[t0 * CAP + p0] = g4.x | ((s4.x & 31) << 15);
    if (p1 < CAP) d_entry[t1 * CAP + p1] = g4.y | ((s4.y & 31) << 15);
    if (p2 < CAP) d_entry[t2 * CAP + p2] = g4.z | ((s4.z & 31) << 15);
    if (p3 < CAP) d_entry[t3 * CAP + p3] = g4.w | ((s4.w & 31) << 15);
}

// ---------------- fused transpose + scatter ----------------
__global__ void __launch_bounds__(256)
fused_scatter_kernel(const float* __restrict__ snp,
                     const float* __restrict__ filters) {
    __shared__ float tile[32][68];
    __shared__ float wv[32];
    const int s0 = blockIdx.x * 32;
    const int t  = threadIdx.x;

    int total = d_cur[blockIdx.x];   // early: overlaps transpose

    if (t < 32) {
        float acc = 0.f;
#pragma unroll
        for (int f = 0; f < 8; f++) acc += filters[(size_t)f * NS + s0 + t];
        wv[t] = acc * 0.125f;
    }
    {
        const int sl = t & 31, brow = t >> 5;
#pragma unroll
        for (int i = 0; i < 8; i++) {
            int b = brow + i * 8;
            tile[sl][b] = snp[(size_t)b * NS + s0 + sl];
        }
    }
    __syncthreads();

    const int base = blockIdx.x * CAP;
    if (total > CAP) total = CAP;
    const int q = t & 15;

    for (int c = t >> 4; c < total; c += 16) {
        int v  = d_entry[base + c];
        int g  = v & 0x7FFF;
        int sl = v >> 15;
        float w = wv[sl];
        float4 x = *reinterpret_cast<const float4*>(&tile[sl][q * 4]);
        red_add_v4(&d_geneT[g * NB + q * 4], x.x * w, x.y * w, x.z * w, x.w * w);
    }
}

// ---------------- GEMM1: tf32, cp.async 3-stage pipeline ----------------
#define WSZ (16 * 136)   // words per W stage (padded)
#define GSZ (16 * 72)    // words per gene stage (padded)

__global__ void __launch_bounds__(256)
gemm1_tf32_kernel(const float* __restrict__ gene,
                  const float* __restrict__ W1,
                  float* __restrict__ C,
                  int kchunk) {
    __shared__ float Ws[3][16][136];   // raw fp32 W1 tiles
    __shared__ float Gs[3][16][72];    // raw fp32 gene tiles

    const int f0 = blockIdx.x * 128;
    const int k0 = blockIdx.y * kchunk;
    const int t  = threadIdx.x;
    const int w  = t >> 5, l = t & 31;
    const int g4 = l >> 2, tg = l & 3;

    float acc[8][4] = {};

    const int aBase = tg * 136 + w * 16 + g4;
    const int bBase = tg * 72 + g4;

    // staging indices
    const int gRow = t >> 4,   gCol = (t & 15) * 4;        // gene 16x64
    const int wRow0 = t >> 5,  wCol = (t & 31) * 4;        // W 16x128, 2 halves
    const int wRow1 = wRow0 + 8;

    const unsigned int gsA = (unsigned int)__cvta_generic_to_shared(&Gs[0][0][0]);
    const unsigned int wsA = (unsigned int)__cvta_generic_to_shared(&Ws[0][0][0]);
    const unsigned int gsDst = gsA + (gRow * 72 + gCol) * 4;
    const unsigned int wsDst0 = wsA + (wRow0 * 136 + wCol) * 4;
    const unsigned int wsDst1 = wsA + (wRow1 * 136 + wCol) * 4;

    const int iters = kchunk >> 4;

    // prologue: stages 0 and 1
#pragma unroll
    for (int s = 0; s < 2; s++) {
        const int kb = k0 + s * 16;
        cp_async16(gsDst + s * GSZ * 4, &gene[(size_t)(kb + gRow) * NB + gCol]);
        cp_async16(wsDst0 + s * WSZ * 4, &W1[(size_t)(kb + wRow0) * H1 + f0 + wCol]);
        cp_async16(wsDst1 + s * WSZ * 4, &W1[(size_t)(kb + wRow1) * H1 + f0 + wCol]);
        cp_commit();
    }

    int buf = 0;
    for (int it = 0; it < iters; it++) {
        cp_wait1();            // stage `it` resident (uniform commit groups)
        __syncthreads();       // visible to all warps; all warps done with buf of it-1

        if (it + 2 < iters) {  // prefetch stage it+2 into ring slot (it+2)%3
            const int kb = k0 + (it + 2) * 16;
            const int s = (it + 2) % 3;
            cp_async16(gsDst + s * GSZ * 4, &gene[(size_t)(kb + gRow) * NB + gCol]);
            cp_async16(wsDst0 + s * WSZ * 4, &W1[(size_t)(kb + wRow0) * H1 + f0 + wCol]);
            cp_async16(wsDst1 + s * WSZ * 4, &W1[(size_t)(kb + wRow1) * H1 + f0 + wCol]);
        }
        cp_commit();           // always commit (empty groups keep counts uniform)

        const float* wsF = &Ws[buf][0][0];
        const float* gsF = &Gs[buf][0][0];
#pragma unroll
        for (int ks = 0; ks < 2; ks++) {
            const float* pa = wsF + aBase + ks * (8 * 136);
            unsigned int a0 = to_tf32(pa[0]);
            unsigned int a1 = to_tf32(pa[8]);
            unsigned int a2 = to_tf32(pa[4 * 136]);
            unsigned int a3 = to_tf32(pa[4 * 136 + 8]);
            const float* pb = gsF + bBase + ks * (8 * 72);
#pragma unroll
            for (int j = 0; j < 8; j++) {
                unsigned int b0 = to_tf32(pb[j * 8]);
                unsigned int b1 = to_tf32(pb[j * 8 + 4 * 72]);
                mma_tf32(acc[j][0], acc[j][1], acc[j][2], acc[j][3],
                         a0, a1, a2, a3, b0, b1);
            }
        }
        buf = (buf + 1) % 3;
    }

    const int featA = f0 + w * 16 + g4;
    const int bcol0 = tg * 2;
#pragma unroll
    for (int j = 0; j < 8; j++) {
        float* cp = &C[(size_t)featA * NB + j * 8 + bcol0];
        red_add_v2(cp, acc[j][0], acc[j][1]);
        red_add_v2(cp + 8 * NB, acc[j][2], acc[j][3]);
    }
}

// ---------------- GEMM2 (f32x2, 64m x 128n tile, split-K with red.v4) ----------------
__global__ void __launch_bounds__(256)
gemm_kernel(const float* __restrict__ A,
            const float* __restrict__ W,
            float* __restrict__ C,
            int N, int kchunk) {
    __shared__ float As[16][64];
    __shared__ float Bs[16][128];

    const int n0 = blockIdx.x * 128;
    const int k0 = blockIdx.y * kchunk;
    const int t  = threadIdx.x;
    const int w  = t >> 5, l = t & 31;

    unsigned long long acc[4][4] = {};

    const float4* A4 = reinterpret_cast<const float4*>(A);
    const float4* W4 = reinterpret_cast<const float4*>(W);
    const int n4 = N >> 2;

    const int arow = t >> 4, ac = t & 15;
    const int brow = t >> 5, bc = t & 31;

    for (int kc = 0; kc < kchunk; kc += 16) {
        const int kb = k0 + kc;
        reinterpret_cast<float4*>(&As[arow][0])[ac] =
            A4[(size_t)(kb + arow) * 16 + ac];
        reinterpret_cast<float4*>(&Bs[brow][0])[bc] =
            W4[(size_t)(kb + brow) * n4 + (n0 >> 2) + bc];
        reinterpret_cast<float4*>(&Bs[brow + 8][0])[bc] =
            W4[(size_t)(kb + brow + 8) * n4 + (n0 >> 2) + bc];
        __syncthreads();

#pragma unroll
        for (int kk = 0; kk < 16; kk++) {
            ulonglong2 a01 = reinterpret_cast<const ulonglong2*>(&As[kk][w * 8])[0];
            ulonglong2 a23 = reinterpret_cast<const ulonglong2*>(&As[kk][w * 8])[1];
            float4 bv = reinterpret_cast<const float4*>(&Bs[kk][0])[l];
            unsigned long long b0 = splat2(bv.x), b1 = splat2(bv.y);
            unsigned long long b2 = splat2(bv.z), b3 = splat2(bv.w);

            acc[0][0] = fma2(a01.x, b0, acc[0][0]);
            acc[0][1] = fma2(a01.y, b0, acc[0][1]);
            acc[0][2] = fma2(a23.x, b0, acc[0][2]);
            acc[0][3] = fma2(a23.y, b0, acc[0][3]);
            acc[1][0] = fma2(a01.x, b1, acc[1][0]);
            acc[1][1] = fma2(a01.y, b1, acc[1][1]);
            acc[1][2] = fma2(a23.x, b1, acc[1][2]);
            acc[1][3] = fma2(a23.y, b1, acc[1][3]);
            acc[2][0] = fma2(a01.x, b2, acc[2][0]);
            acc[2][1] = fma2(a01.y, b2, acc[2][1]);
            acc[2][2] = fma2(a23.x, b2, acc[2][2]);
            acc[2][3] = fma2(a23.y, b2, acc[2][3]);
            acc[3][0] = fma2(a01.x, b3, acc[3][0]);
            acc[3][1] = fma2(a01.y, b3, acc[3][1]);
            acc[3][2] = fma2(a23.x, b3, acc[3][2]);
            acc[3][3] = fma2(a23.y, b3, acc[3][3]);
        }
        __syncthreads();
    }

#pragma unroll
    for (int i = 0; i < 4; i++) {
        int n = n0 + l * 4 + i;
        float* cp = &C[(size_t)n * NB + w * 8];
        float2 p0 = *reinterpret_cast<float2*>(&acc[i][0]);
        float2 p1 = *reinterpret_cast<float2*>(&acc[i][1]);
        float2 p2 = *reinterpret_cast<float2*>(&acc[i][2]);
        float2 p3 = *reinterpret_cast<float2*>(&acc[i][3]);
        red_add_v4(cp,     p0.x, p0.y, p1.x, p1.y);
        red_add_v4(cp + 4, p2.x, p2.y, p3.x, p3.y);
    }
}

// ---------------- batchnorm + relu (h1 only) ----------------
__global__ void bn_relu_kernel(float* __restrict__ h,
                               const float* __restrict__ gamma,
                               const float* __restrict__ beta, int R) {
    int warp = (blockIdx.x * blockDim.x + threadIdx.x) >> 5;
    int lane = threadIdx.x & 31;
    if (warp >= R) return;
    float* row = h + warp * NB;
    float x0 = row[lane], x1 = row[lane + 32];
    float s = x0 + x1, sq = x0 * x0 + x1 * x1;
#pragma unroll
    for (int o = 16; o; o >>= 1) {
        s  += __shfl_xor_sync(0xffffffffu, s, o);
        sq += __shfl_xor_sync(0xffffffffu, sq, o);
    }
    float m = s * (1.f / 64.f);
    float v = sq * (1.f / 64.f) - m * m;
    float inv = rsqrtf(v + 1e-5f);
    float g = gamma[warp], be = beta[warp];
    row[lane]      = fmaxf(fmaf(g * (x0 - m), inv, be), 0.f);
    row[lane + 32] = fmaxf(fmaf(g * (x1 - m), inv, be), 0.f);
}

// ---------------- fused bn2 + relu + final projection ----------------
__global__ void bn_final_kernel(const float* __restrict__ gamma,
                                const float* __restrict__ beta,
                                const float* __restrict__ W3,
                                const float* __restrict__ b3,
                                float* __restrict__ out) {
    __shared__ float part[8][NB];
    const int t = threadIdx.x, lane = t & 31, w = t >> 5;
    float a0 = 0.f, a1 = 0.f;
#pragma unroll 4
    for (int r = 0; r < 32; r++) {
        int p = w * 32 + r;
        float x0 = d_h2v[p * NB + lane];
        float x1 = d_h2v[p * NB + lane + 32];
        float s = x0 + x1, sq = x0 * x0 + x1 * x1;
#pragma unroll
        for (int o = 16; o; o >>= 1) {
            s  += __shfl_xor_sync(0xffffffffu, s, o);
            sq += __shfl_xor_sync(0xffffffffu, sq, o);
        }
        float m = s * (1.f / 64.f);
        float v = sq * (1.f / 64.f) - m * m;
        float inv = rsqrtf(v + 1e-5f);
        float g = gamma[p], be = beta[p], w3 = W3[p];
        a0 += fmaxf(fmaf(g * (x0 - m), inv, be), 0.f) * w3;
        a1 += fmaxf(fmaf(g * (x1 - m), inv, be), 0.f) * w3;
    }
    part[w][lane] = a0;
    part[w][lane + 32] = a1;
    __syncthreads();
    if (t < NB) {
        float s = b3[0];
#pragma unroll
        for (int i = 0; i < 8; i++) s += part[i][t];
        out[t] = s;
    }
}

// ---------------- launch ----------------
extern "C" void kernel_launch(void* const* d_in, const int* in_sizes, int n_in,
                              void* d_out, int out_size) {
    const float* snp       = (const float*)d_in[0];
    const int*   snp_ids   = (const int*)  d_in[1];
    const int*   node_gene = (const int*)  d_in[2];
    const float* filters   = (const float*)d_in[3];
    const float* W1        = (const float*)d_in[4];
    // b1 = d_in[5] (cancels under batch-stat BN)
    const float* g1        = (const float*)d_in[6];
    const float* beta1     = (const float*)d_in[7];
    const float* W2        = (const float*)d_in[8];
    // b2 = d_in[9] (cancels)
    const float* g2        = (const float*)d_in[10];
    const float* beta2     = (const float*)d_in[11];
    const float* W3        = (const float*)d_in[12];
    const float* b3        = (const float*)d_in[13];
    float* out = (float*)d_out;

    void *pGene = nullptr, *pH1 = nullptr, *pH2 = nullptr;
    cudaGetSymbolAddress(&pGene, d_geneT);
    cudaGetSymbolAddress(&pH1,   d_h1v);
    cudaGetSymbolAddress(&pH2,   d_h2v);

    {
        const int total = NGENES * NB + H1 * NB + H2 * NB + NT;
        zero_kernel<<<(total + 255) / 256, 256>>>();
    }

    // bucket fill (fixed-capacity CSR, no histogram/scan)
    fill_kernel<<<(NNODES / 4 + 255) / 256, 256>>>(snp_ids, node_gene);

    // fused transpose + scatter
    fused_scatter_kernel<<<NT, 256>>>(snp, filters);

    // GEMM1: tf32 tensor cores, cp.async pipelined. 8 feat-tiles x 125 k-splits
    gemm1_tf32_kernel<<<dim3(8, 125), 256>>>((const float*)pGene, W1, (float*)pH1, 160);
    bn_relu_kernel<<<H1 * 32 / 256, 256>>>((float*)pH1, g1, beta1, H1);

    // GEMM2: N=256 -> 2 n-tiles; K=1024 split 16 x 64
    gemm_kernel<<<dim3(2, 16), 256>>>((const float*)pH1, W2, (float*)pH2, 256, 64);

    // fused bn2 + relu + final projection
    bn_final_kernel<<<1, 256>>>(g2, beta2, W3, b3, out);

    // second reference output: filters passthrough
    if (out_size > NB) {
        cudaMemcpyAsync(out + NB, filters,
                        (size_t)(out_size - NB) * sizeof(float),
                        cudaMemcpyDeviceToDevice);
    }
}